// round 13
// baseline (speedup 1.0000x reference)
#include <cuda_runtime.h>

// Shape: B = 65536 rows, C = 1000 fp32 classes. 250 float4 per row.
#define NCLS    1000
#define TPB     32
#define MAXGRID 8192

__device__ double   g_part[MAXGRID];
__device__ unsigned g_ticket = 0;

__device__ __forceinline__ float warp_sum(float v) {
    #pragma unroll
    for (int o = 16; o > 0; o >>= 1) v += __shfl_xor_sync(0xffffffffu, v, o);
    return v;
}
__device__ __forceinline__ double warp_sum_d(double v) {
    #pragma unroll
    for (int o = 16; o > 0; o >>= 1) v += __shfl_xor_sync(0xffffffffu, v, o);
    return v;
}

__global__ void __launch_bounds__(TPB)
mvce_warp(const float* __restrict__ outp, const float* __restrict__ tgt,
          float* __restrict__ result, int B, int nwarps) {
    const int lane = threadIdx.x;
    const int gw   = blockIdx.x;

    double acc = 0.0;

    for (int row = gw; row < B; row += nwarps) {
        const float4* __restrict__ o4 =
            reinterpret_cast<const float4*>(outp + (size_t)row * NCLS);
        const float4* __restrict__ t4 =
            reinterpret_cast<const float4*>(tgt  + (size_t)row * NCLS);

        // Register-resident row. ov holds o, later overwritten in place by e=exp(o).
        float4 ov[8], tv[8];

        // ---- front-batched loads: 16 independent LDG.128 in flight ----
        #pragma unroll
        for (int k = 0; k < 8; k++) {
            const int  idx   = k * 32 + lane;
            const bool valid = (k < 7) || (lane < 26);   // 250 float4/row
            ov[k] = valid ? o4[idx] : make_float4(0.f, 0.f, 0.f, 0.f);
        }
        #pragma unroll
        for (int k = 0; k < 8; k++) {
            const int  idx   = k * 32 + lane;
            const bool valid = (k < 7) || (lane < 26);
            tv[k] = valid ? t4[idx] : make_float4(0.f, 0.f, 0.f, 0.f);
        }

        // ---- pass A: accumulate stats; overwrite o with e = exp(o) ----
        float s = 0.f, tn = 0.f, an = 0.f, ap = 0.f, np = 0.f;
        #pragma unroll
        for (int k = 0; k < 8; k++) {
            float o_[4] = {ov[k].x, ov[k].y, ov[k].z, ov[k].w};
            float t_[4] = {tv[k].x, tv[k].y, tv[k].z, tv[k].w};
            float e_[4];
            #pragma unroll
            for (int j = 0; j < 4; j++) {
                e_[j] = __expf(o_[j]);           // padded tail: exp(0)=1 but t=0 -> neg path adds e; guard below
                float to = t_[j] * o_[j];
                if (t_[j] > 0.5f) {              // positive
                    ap += to;
                    np += 1.0f;
                } else {                         // negative
                    s  += e_[j];
                    tn += t_[j];
                    an += to;
                }
            }
            ov[k].x = e_[0]; ov[k].y = e_[1]; ov[k].z = e_[2]; ov[k].w = e_[3];
        }
        // Padded-tail correction: 6 lanes (26..31) in chunk 7 contributed
        // exp(0)=1 each to s via the negative path. Subtract deterministically.
        if (lane == 0) s -= 24.0f;               // 6 lanes * 4 elements * 1.0

        // ---- warp butterflies (no barriers; all lanes get totals) ----
        const float Sneg = warp_sum(s);
        const float Tneg = warp_sum(tn);
        const float Aneg = warp_sum(an);

        // ---- pass B: sum over positives of (Tneg + t_p) * log(Sneg + e_p) ----
        float L = 0.f;
        #pragma unroll
        for (int k = 0; k < 8; k++) {
            if (tv[k].x > 0.5f) L = fmaf(Tneg + tv[k].x, __logf(Sneg + ov[k].x), L);
            if (tv[k].y > 0.5f) L = fmaf(Tneg + tv[k].y, __logf(Sneg + ov[k].y), L);
            if (tv[k].z > 0.5f) L = fmaf(Tneg + tv[k].z, __logf(Sneg + ov[k].z), L);
            if (tv[k].w > 0.5f) L = fmaf(Tneg + tv[k].w, __logf(Sneg + ov[k].w), L);
        }

        const float Lt  = warp_sum(L);
        const float apT = warp_sum(ap);
        const float npT = warp_sum(np);

        float r;
        if (npT > 0.0f) {
            r = (Lt - npT * Aneg - apT) / npT;
        } else {
            r = Tneg * __logf(Sneg) - Aneg;      // no-positive fallback
        }
        acc += (double)r;
    }

    // ---- per-warp partial + fused deterministic fan-in ----
    if (lane == 0) g_part[gw] = acc;

    unsigned isLast = 0;
    if (lane == 0) {
        __threadfence();
        if (atomicAdd(&g_ticket, 1u) == (unsigned)(gridDim.x - 1)) isLast = 1;
    }
    isLast = __shfl_sync(0xffffffffu, isLast, 0);

    if (isLast) {
        __threadfence();                         // see all partials
        const int n = gridDim.x;
        double a = 0.0;
        for (int i = lane; i < n; i += 32)       // fixed order -> deterministic
            a += g_part[i];
        a = warp_sum_d(a);
        if (lane == 0) {
            result[0] = (float)(a / (double)B);
            g_ticket = 0;                        // reset for next graph replay
        }
    }
}

extern "C" void kernel_launch(void* const* d_in, const int* in_sizes, int n_in,
                              void* d_out, int out_size) {
    const float* output = (const float*)d_in[0];
    const float* target = (const float*)d_in[1];
    float* out = (float*)d_out;

    const int B = in_sizes[0] / NCLS;

    // 96-reg kernel -> 5 warps/SMSP -> 20 warp-CTAs/SM; fill exactly that.
    int grid = 148 * 20;
    if (grid > B) grid = B;
    if (grid > MAXGRID) grid = MAXGRID;
    if (grid < 1) grid = 1;

    mvce_warp<<<grid, TPB>>>(output, target, out, B, grid);
}

// round 14
// speedup vs baseline: 2.2314x; 2.2314x over previous
#include <cuda_runtime.h>

// Shape: B = 65536 rows, C = 1000 fp32 classes. 250 float4 per row.
#define NCLS    1000
#define NF4     250
#define TPB     32
#define MAXGRID 8192

__device__ double   g_part[MAXGRID];
__device__ unsigned g_ticket = 0;

__device__ __forceinline__ float warp_sum(float v) {
    #pragma unroll
    for (int o = 16; o > 0; o >>= 1) v += __shfl_xor_sync(0xffffffffu, v, o);
    return v;
}
__device__ __forceinline__ double warp_sum_d(double v) {
    #pragma unroll
    for (int o = 16; o > 0; o >>= 1) v += __shfl_xor_sync(0xffffffffu, v, o);
    return v;
}

__global__ void __launch_bounds__(TPB)
mvce_warp(const float* __restrict__ outp, const float* __restrict__ tgt,
          float* __restrict__ result, int B, int nwarps) {
    const int lane = threadIdx.x;
    const int gw   = blockIdx.x;

    // Row scratch: (e, masked_t) per element. Thread-local access pattern
    // (each lane reads back only what it wrote) -> no sync ever needed.
    __shared__ float2 sh[NCLS];                  // 8000 B

    double acc = 0.0;

    for (int row = gw; row < B; row += nwarps) {
        const float4* __restrict__ o4 =
            reinterpret_cast<const float4*>(outp + (size_t)row * NCLS);
        const float4* __restrict__ t4 =
            reinterpret_cast<const float4*>(tgt  + (size_t)row * NCLS);

        // ---- pass A: stream chunks; accumulate stats; park (e, t+) in smem ----
        float s = 0.f, tn = 0.f, an = 0.f, ap = 0.f, np = 0.f;
        #pragma unroll
        for (int k = 0; k < 8; k++) {
            const int  idx   = k * 32 + lane;
            const bool valid = (k < 7) || (lane < 26);   // 250 float4/row
            float4 ov = valid ? o4[idx] : make_float4(0.f, 0.f, 0.f, 0.f);
            float4 tv = valid ? t4[idx] : make_float4(0.f, 0.f, 0.f, 0.f);

            float o_[4] = {ov.x, ov.y, ov.z, ov.w};
            float t_[4] = {tv.x, tv.y, tv.z, tv.w};
            #pragma unroll
            for (int j = 0; j < 4; j++) {
                float e  = valid ? __expf(o_[j]) : 0.0f;
                float to = t_[j] * o_[j];
                float tm;
                if (t_[j] > 0.5f) {              // positive
                    ap += to;
                    np += 1.0f;
                    tm  = t_[j];
                } else {                          // negative (padded tail: e=0,t=0)
                    s  += e;
                    tn += t_[j];
                    an += to;
                    tm  = 0.0f;
                }
                if (valid) sh[idx * 4 + j] = make_float2(e, tm);
            }
        }

        // ---- warp butterflies (all lanes get totals; no barriers) ----
        const float Sneg = warp_sum(s);
        const float Tneg = warp_sum(tn);
        const float Aneg = warp_sum(an);

        // ---- pass B: positives only: sum (Tneg + t_p) * log(Sneg + e_p) ----
        float L = 0.f;
        #pragma unroll
        for (int k = 0; k < 8; k++) {
            const int  idx   = k * 32 + lane;
            const bool valid = (k < 7) || (lane < 26);
            if (valid) {
                #pragma unroll
                for (int j = 0; j < 4; j++) {
                    float2 p = sh[idx * 4 + j];
                    if (p.y > 0.5f)
                        L = fmaf(Tneg + p.y, __logf(Sneg + p.x), L);
                }
            }
        }

        const float Lt  = warp_sum(L);
        const float apT = warp_sum(ap);
        const float npT = warp_sum(np);

        float r;
        if (npT > 0.0f) {
            r = (Lt - npT * Aneg - apT) / npT;
        } else {
            r = Tneg * __logf(Sneg) - Aneg;      // no-positive fallback
        }
        acc += (double)r;
    }

    // ---- per-warp partial + fused deterministic fan-in ----
    if (lane == 0) g_part[gw] = acc;

    unsigned isLast = 0;
    if (lane == 0) {
        __threadfence();
        if (atomicAdd(&g_ticket, 1u) == (unsigned)(gridDim.x - 1)) isLast = 1;
    }
    isLast = __shfl_sync(0xffffffffu, isLast, 0);

    if (isLast) {
        __threadfence();                         // see all partials
        const int n = gridDim.x;
        double a = 0.0;
        for (int i = lane; i < n; i += 32)       // fixed order -> deterministic
            a += g_part[i];
        a = warp_sum_d(a);
        if (lane == 0) {
            result[0] = (float)(a / (double)B);
            g_ticket = 0;                        // reset for next graph replay
        }
    }
}

extern "C" void kernel_launch(void* const* d_in, const int* in_sizes, int n_in,
                              void* d_out, int out_size) {
    const float* output = (const float*)d_in[0];
    const float* target = (const float*)d_in[1];
    float* out = (float*)d_out;

    const int B = in_sizes[0] / NCLS;

    int dev = 0;
    cudaGetDevice(&dev);
    int sms = 148;
    cudaDeviceGetAttribute(&sms, cudaDevAttrMultiProcessorCount, dev);
    int nb = 0;
    cudaOccupancyMaxActiveBlocksPerMultiprocessor(&nb, mvce_warp, TPB, 0);
    if (nb < 1) nb = 1;

    int grid = sms * nb;                 // exactly one resident wave
    if (grid > B) grid = B;
    if (grid > MAXGRID) grid = MAXGRID;
    if (grid < 1) grid = 1;

    mvce_warp<<<grid, TPB>>>(output, target, out, B, grid);
}

// round 15
// speedup vs baseline: 2.5817x; 1.1570x over previous
#include <cuda_runtime.h>
#include <cstdint>

// Shape: B = 65536 rows, C = 1000 fp32 classes. 250 float4 per row.
#define NCLS    1000
#define TPB     32
#define MAXGRID 8192

__device__ double   g_part[MAXGRID];
__device__ unsigned g_ticket = 0;

__device__ __forceinline__ float warp_sum(float v) {
    #pragma unroll
    for (int o = 16; o > 0; o >>= 1) v += __shfl_xor_sync(0xffffffffu, v, o);
    return v;
}
__device__ __forceinline__ double warp_sum_d(double v) {
    #pragma unroll
    for (int o = 16; o > 0; o >>= 1) v += __shfl_xor_sync(0xffffffffu, v, o);
    return v;
}

// Issue 16-byte cp.async (L2-only .cg: single-use stream, keep L1 cool).
__device__ __forceinline__ void cp16(uint32_t smem, const void* gmem) {
    asm volatile("cp.async.cg.shared.global [%0], [%1], 16;" ::
                 "r"(smem), "l"(gmem));
}
__device__ __forceinline__ void cp_commit() {
    asm volatile("cp.async.commit_group;" ::: "memory");
}
__device__ __forceinline__ void cp_wait1() {
    asm volatile("cp.async.wait_group 1;" ::: "memory");
}

// Prefetch one row's o,t (250 float4 each) into smem buffer via cp.async.
__device__ __forceinline__ void prefetch_row(uint32_t sm_o, uint32_t sm_t,
                                             const float4* __restrict__ o4,
                                             const float4* __restrict__ t4,
                                             int lane) {
    #pragma unroll
    for (int k = 0; k < 8; k++) {
        const int idx = k * 32 + lane;
        if (k < 7 || lane < 26) {               // 250 float4/row
            cp16(sm_o + (uint32_t)idx * 16u, o4 + idx);
            cp16(sm_t + (uint32_t)idx * 16u, t4 + idx);
        }
    }
}

__global__ void __launch_bounds__(TPB)
mvce_warp(const float* __restrict__ outp, const float* __restrict__ tgt,
          float* __restrict__ result, int B, int nwarps) {
    const int lane = threadIdx.x;
    const int gw   = blockIdx.x;

    // Double-buffered raw row: [buf][o|t][256 float4] = 16 KB.
    __shared__ float4 sbuf[2][2][256];

    const uint32_t sb = (uint32_t)__cvta_generic_to_shared(&sbuf[0][0][0]);
    const uint32_t BUFB = 2u * 256u * 16u;       // bytes per buffer (o+t)
    const uint32_t TOFF = 256u * 16u;            // o->t slot offset

    // Zero the 6 padding float4 slots (chunk 7, lanes 26..31) in all buffers
    // so unguarded smem reads see (o=0 -> handled, t=0 -> negative, e forced 0).
    if (lane >= 26) {
        const int idx = 7 * 32 + lane;
        float4 z = make_float4(0.f, 0.f, 0.f, 0.f);
        sbuf[0][0][idx] = z; sbuf[0][1][idx] = z;
        sbuf[1][0][idx] = z; sbuf[1][1][idx] = z;
    }
    __syncwarp();

    double acc = 0.0;
    int cur = 0;

    int row = gw;
    if (row < B) {
        prefetch_row(sb, sb + TOFF,
                     reinterpret_cast<const float4*>(outp + (size_t)row * NCLS),
                     reinterpret_cast<const float4*>(tgt  + (size_t)row * NCLS),
                     lane);
    }
    cp_commit();

    for (; row < B; row += nwarps) {
        // ---- prefetch next row into the other buffer (always commit a group) ----
        const int nxt = row + nwarps;
        const uint32_t nb = sb + (uint32_t)(cur ^ 1) * BUFB;
        if (nxt < B) {
            prefetch_row(nb, nb + TOFF,
                         reinterpret_cast<const float4*>(outp + (size_t)nxt * NCLS),
                         reinterpret_cast<const float4*>(tgt  + (size_t)nxt * NCLS),
                         lane);
        }
        cp_commit();
        cp_wait1();                              // current buffer complete; next in flight

        float4* __restrict__ so = &sbuf[cur][0][0];
        float4* __restrict__ st = &sbuf[cur][1][0];

        // ---- pass A: stats; overwrite o-slot with e = exp(o) in place ----
        float s = 0.f, tn = 0.f, an = 0.f, ap = 0.f, np = 0.f;
        #pragma unroll
        for (int k = 0; k < 8; k++) {
            const int  idx   = k * 32 + lane;
            const bool valid = (k < 7) || (lane < 26);
            float4 ov = so[idx];
            float4 tv = st[idx];
            float o_[4] = {ov.x, ov.y, ov.z, ov.w};
            float t_[4] = {tv.x, tv.y, tv.z, tv.w};
            float e_[4];
            #pragma unroll
            for (int j = 0; j < 4; j++) {
                e_[j] = valid ? __expf(o_[j]) : 0.0f;
                float to = t_[j] * o_[j];
                if (t_[j] > 0.5f) {              // positive
                    ap += to;
                    np += 1.0f;
                } else {                          // negative (padding: e=0,t=0)
                    s  += e_[j];
                    tn += t_[j];
                    an += to;
                }
            }
            so[idx] = make_float4(e_[0], e_[1], e_[2], e_[3]);
        }

        // ---- warp butterflies (no barriers; all lanes get totals) ----
        const float Sneg = warp_sum(s);
        const float Tneg = warp_sum(tn);
        const float Aneg = warp_sum(an);

        // ---- pass B: positives: sum (Tneg + t_p) * log(Sneg + e_p) ----
        float L = 0.f;
        #pragma unroll
        for (int k = 0; k < 8; k++) {
            const int idx = k * 32 + lane;
            float4 e4 = so[idx];                 // e (written by this lane)
            float4 t4v = st[idx];
            if (t4v.x > 0.5f) L = fmaf(Tneg + t4v.x, __logf(Sneg + e4.x), L);
            if (t4v.y > 0.5f) L = fmaf(Tneg + t4v.y, __logf(Sneg + e4.y), L);
            if (t4v.z > 0.5f) L = fmaf(Tneg + t4v.z, __logf(Sneg + e4.z), L);
            if (t4v.w > 0.5f) L = fmaf(Tneg + t4v.w, __logf(Sneg + e4.w), L);
        }

        const float Lt  = warp_sum(L);
        const float apT = warp_sum(ap);
        const float npT = warp_sum(np);

        float r;
        if (npT > 0.0f) {
            r = (Lt - npT * Aneg - apT) / npT;
        } else {
            r = Tneg * __logf(Sneg) - Aneg;      // no-positive fallback
        }
        acc += (double)r;

        cur ^= 1;
    }

    // ---- per-warp partial + fused deterministic fan-in ----
    if (lane == 0) g_part[gw] = acc;

    unsigned isLast = 0;
    if (lane == 0) {
        __threadfence();
        if (atomicAdd(&g_ticket, 1u) == (unsigned)(gridDim.x - 1)) isLast = 1;
    }
    isLast = __shfl_sync(0xffffffffu, isLast, 0);

    if (isLast) {
        __threadfence();                         // see all partials
        const int n = gridDim.x;
        double a = 0.0;
        for (int i = lane; i < n; i += 32)       // fixed order -> deterministic
            a += g_part[i];
        a = warp_sum_d(a);
        if (lane == 0) {
            result[0] = (float)(a / (double)B);
            g_ticket = 0;                        // reset for next graph replay
        }
    }
}

extern "C" void kernel_launch(void* const* d_in, const int* in_sizes, int n_in,
                              void* d_out, int out_size) {
    const float* output = (const float*)d_in[0];
    const float* target = (const float*)d_in[1];
    float* out = (float*)d_out;

    const int B = in_sizes[0] / NCLS;

    int dev = 0;
    cudaGetDevice(&dev);
    int sms = 148;
    cudaDeviceGetAttribute(&sms, cudaDevAttrMultiProcessorCount, dev);
    int nb = 0;
    cudaOccupancyMaxActiveBlocksPerMultiprocessor(&nb, mvce_warp, TPB, 0);
    if (nb < 1) nb = 1;

    int grid = sms * nb;                 // one resident wave (smem-limited ~14/SM)
    if (grid > B) grid = B;
    if (grid > MAXGRID) grid = MAXGRID;
    if (grid < 1) grid = 1;

    mvce_warp<<<grid, TPB>>>(output, target, out, B, grid);
}